// round 1
// baseline (speedup 1.0000x reference)
#include <cuda_runtime.h>
#include <math.h>

// Problem constants
#define BB   16
#define NN   256
#define DD   64      // DIN == DOUT == 64
#define KTOP 128
#define ITILE 4

// Scratch (no device allocations allowed -> __device__ globals)
__device__ float g_agg[BB * NN * DD];
__device__ float g_h[BB * NN * DD];
__device__ float g_scores[BB * NN];

// ---------- packed f32x2 helpers (FFMA2 only reachable via PTX) ----------
__device__ __forceinline__ unsigned long long pack2f(float a, float b) {
    unsigned long long r;
    asm("mov.b64 %0, {%1, %2};" : "=l"(r) : "f"(a), "f"(b));
    return r;
}
__device__ __forceinline__ void fma2(unsigned long long& d,
                                     unsigned long long a,
                                     unsigned long long b) {
    asm("fma.rn.f32x2 %0, %1, %2, %0;" : "+l"(d) : "l"(a), "l"(b));
}
__device__ __forceinline__ float2 unpack2f(unsigned long long v) {
    float lo, hi;
    asm("mov.b64 {%0, %1}, %2;" : "=f"(lo), "=f"(hi) : "l"(v));
    float2 r; r.x = lo; r.y = hi;
    return r;
}

// Shared memory layout for kernel 1 (bytes)
//  xT   : 64 * 257 floats  = 65792   (row-pad 257 -> conflict-free both phases)
//  w2   : 64 * 32  u64     = 16384   (W_att packed as f32x2 pairs)
//  aw   : 64 floats
//  bat  : 64 floats
//  A_s  : 256 floats
//  part : 256 floats
//  red  : 32 floats
#define SM_XT    0
#define SM_W2    65792
#define SM_AW    (SM_W2 + 16384)
#define SM_BAT   (SM_AW + 256)
#define SM_AS    (SM_BAT + 256)
#define SM_PART  (SM_AS + 1024)
#define SM_RED   (SM_PART + 1024)
#define SM_TOTAL (SM_RED + 128)

// =====================================================================
// Kernel 1: attention logits + softmax + aggregation
// grid (N/ITILE, B), block 256. One CTA: one batch b, ITILE values of i.
// thread j (=tid) computes logits[b,i,j] for each i in the tile.
// =====================================================================
__global__ __launch_bounds__(256, 2)
void k1_attention(const float* __restrict__ x,
                  const float* __restrict__ Watt,
                  const float* __restrict__ batt_g,
                  const float* __restrict__ attw_g)
{
    extern __shared__ char sm[];
    float* xT               = (float*)(sm + SM_XT);
    unsigned long long* w2  = (unsigned long long*)(sm + SM_W2);
    float* aw               = (float*)(sm + SM_AW);
    float* bat              = (float*)(sm + SM_BAT);
    float* A_s              = (float*)(sm + SM_AS);
    float* part             = (float*)(sm + SM_PART);
    float* red              = (float*)(sm + SM_RED);

    const int tid = threadIdx.x;
    const int b   = blockIdx.y;
    const int lane = tid & 31, warp = tid >> 5;

    // Load x[b] transposed into SMEM: xT[d][j], row stride 257 (conflict-free)
    const float* xb = x + b * (NN * DD);
    for (int idx = tid; idx < NN * DD; idx += 256) {
        int d = idx & 63, jj = idx >> 6;
        xT[d * 257 + jj] = xb[idx];
    }
    // Pack W_att rows into f32x2 pairs
    const float2* Wf2 = (const float2*)Watt;
    for (int idx = tid; idx < 2048; idx += 256) {
        float2 v = Wf2[idx];
        w2[idx] = pack2f(v.x, v.y);
    }
    if (tid < 64) { aw[tid] = attw_g[tid]; bat[tid] = batt_g[tid]; }
    __syncthreads();

    for (int ii = 0; ii < ITILE; ++ii) {
        const int ig = blockIdx.x * ITILE + ii;

        unsigned long long acc[32];
        #pragma unroll
        for (int e = 0; e < 32; ++e) acc[e] = 0ull;

        // Inner GEMM: acc[e] += (x_j[d]*y_i[d]) * W[d][e]  (f32x2 packed over e)
        #pragma unroll 4
        for (int d = 0; d < 64; ++d) {
            float xj = xT[d * 257 + tid];
            float yi = xT[d * 257 + ig];
            float p  = xj * yi;
            unsigned long long pp = pack2f(p, p);
            const ulonglong2* wr = (const ulonglong2*)(w2 + d * 32);
            #pragma unroll
            for (int e = 0; e < 16; ++e) {
                ulonglong2 wv = wr[e];
                fma2(acc[2 * e + 0], pp, wv.x);
                fma2(acc[2 * e + 1], pp, wv.y);
            }
        }

        // tanh + dot with att_w, temperature 2.0
        float logit = 0.f;
        #pragma unroll
        for (int e = 0; e < 32; ++e) {
            float2 v = unpack2f(acc[e]);
            float t0 = tanhf(v.x + bat[2 * e + 0]);
            float t1 = tanhf(v.y + bat[2 * e + 1]);
            logit += t0 * aw[2 * e + 0] + t1 * aw[2 * e + 1];
        }
        logit *= 0.5f;

        // ---- softmax over the 256 threads (axis j) ----
        float m = logit;
        #pragma unroll
        for (int o = 16; o; o >>= 1) m = fmaxf(m, __shfl_xor_sync(0xffffffffu, m, o));
        if (lane == 0) red[warp] = m;
        __syncthreads();
        m = red[0];
        #pragma unroll
        for (int w = 1; w < 8; ++w) m = fmaxf(m, red[w]);
        float ex = expf(logit - m);
        float s = ex;
        #pragma unroll
        for (int o = 16; o; o >>= 1) s += __shfl_xor_sync(0xffffffffu, s, o);
        __syncthreads();   // all max-reads done before red is overwritten
        if (lane == 0) red[warp] = s;
        __syncthreads();
        s = 0.f;
        #pragma unroll
        for (int w = 0; w < 8; ++w) s += red[w];
        float A = ex / s;
        A_s[tid] = A;
        __syncthreads();

        // ---- agg[d] = sum_j A[j] * x[b][j][d] ----
        {
            int d = tid & 63, q = tid >> 6;
            const float* xrow = xT + d * 257 + q * 64;
            const float* Aq   = A_s + q * 64;
            float pa = 0.f;
            #pragma unroll 8
            for (int jj = 0; jj < 64; ++jj) pa = fmaf(Aq[jj], xrow[jj], pa);
            part[tid] = pa;
        }
        __syncthreads();
        if (tid < 64) {
            float a = part[tid] + part[tid + 64] + part[tid + 128] + part[tid + 192];
            g_agg[(b * NN + ig) * DD + tid] = a;
        }
        __syncthreads();
    }
}

// =====================================================================
// Kernel 2: h = agg@W_pwa + b_pwa + x@W_pna + b_pna ; BN ; SELU ; scores
// grid B*N/4 blocks of 256 (4 nodes per block, 64 threads each)
// =====================================================================
__global__ __launch_bounds__(256)
void k2_linear(const float* __restrict__ x,
               const float* __restrict__ Wpwa, const float* __restrict__ bpwa,
               const float* __restrict__ Wpna, const float* __restrict__ bpna,
               const float* __restrict__ bnsc, const float* __restrict__ bnbi,
               const float* __restrict__ poolw, const float* __restrict__ poolb)
{
    __shared__ float redsm[8];
    const int tid = threadIdx.x;
    const int g = tid >> 6, e = tid & 63;
    const int ilin = blockIdx.x * 4 + g;         // 0 .. B*N-1
    const float* agg = g_agg + ilin * DD;
    const float* xi  = x + ilin * DD;

    float h = bpwa[e] + bpna[e];
    #pragma unroll 8
    for (int d = 0; d < 64; ++d) {
        h = fmaf(__ldg(agg + d), __ldg(Wpwa + d * 64 + e), h);
        h = fmaf(__ldg(xi + d),  __ldg(Wpna + d * 64 + e), h);
    }
    // BatchNorm eval (running_mean=0, running_var=1)
    h = h * (bnsc[e] * rsqrtf(1.0f + 1e-5f)) + bnbi[e];
    // SELU
    h = 1.0507009873554805f *
        (h > 0.f ? h : 1.6732632423543772f * (expf(h) - 1.f));
    g_h[ilin * DD + e] = h;

    // score = sigmoid(h . pool_w + pool_b), reduced over the 64-thread group
    float r = h * poolw[e];
    #pragma unroll
    for (int o = 16; o; o >>= 1) r += __shfl_xor_sync(0xffffffffu, r, o);
    const int lane = tid & 31, warp = tid >> 5;
    if (lane == 0) redsm[warp] = r;
    __syncthreads();
    if (e == 0) {
        float z = redsm[g * 2] + redsm[g * 2 + 1] + poolb[0];
        g_scores[ilin] = 1.f / (1.f + expf(-z));
    }
}

// =====================================================================
// Kernel 3: stable top-k (descending, low index wins ties == jax.lax.top_k)
// + gather of h * score. grid B blocks of 256.
// =====================================================================
__global__ __launch_bounds__(256)
void k3_topk(float* __restrict__ out)
{
    __shared__ float sc[NN];
    __shared__ int src[KTOP];
    const int tid = threadIdx.x;
    const int b = blockIdx.x;

    float s = g_scores[b * NN + tid];
    sc[tid] = s;
    __syncthreads();

    int rank = 0;
    #pragma unroll 8
    for (int j = 0; j < NN; ++j) {
        float sj = sc[j];
        rank += (sj > s) || (sj == s && j < tid);
    }
    if (rank < KTOP) src[rank] = tid;
    __syncthreads();

    for (int idx = tid; idx < KTOP * DD; idx += 256) {
        int r = idx >> 6, e = idx & 63;
        int j = src[r];
        out[b * (KTOP * DD) + idx] = g_h[(b * NN + j) * DD + e] * sc[j];
    }
}

// =====================================================================
extern "C" void kernel_launch(void* const* d_in, const int* in_sizes, int n_in,
                              void* d_out, int out_size)
{
    const float* x     = (const float*)d_in[0];
    const float* Watt  = (const float*)d_in[1];
    const float* batt  = (const float*)d_in[2];
    const float* attw  = (const float*)d_in[3];
    const float* Wpwa  = (const float*)d_in[4];
    const float* bpwa  = (const float*)d_in[5];
    const float* Wpna  = (const float*)d_in[6];
    const float* bpna  = (const float*)d_in[7];
    const float* bnsc  = (const float*)d_in[8];
    const float* bnbi  = (const float*)d_in[9];
    const float* poolw = (const float*)d_in[10];
    const float* poolb = (const float*)d_in[11];

    cudaFuncSetAttribute(k1_attention,
                         cudaFuncAttributeMaxDynamicSharedMemorySize, SM_TOTAL);

    dim3 g1(NN / ITILE, BB);
    k1_attention<<<g1, 256, SM_TOTAL>>>(x, Watt, batt, attw);
    k2_linear<<<(BB * NN) / 4, 256>>>(x, Wpwa, bpwa, Wpna, bpna,
                                      bnsc, bnbi, poolw, poolb);
    k3_topk<<<BB, 256>>>((float*)d_out);
}

// round 4
// speedup vs baseline: 1.0919x; 1.0919x over previous
#include <cuda_runtime.h>
#include <math.h>
#include <stdint.h>

#define BB   16
#define NN   256
#define DD   64
#define KTOP 128

// Scratch (no device allocations allowed)
__device__ float g_agg[BB * NN * DD];
__device__ float g_h[BB * NN * DD];
__device__ float g_scores[BB * NN];

// ---------------- packed f32x2 helpers ----------------
__device__ __forceinline__ unsigned long long pack2f(float a, float b) {
    unsigned long long r;
    asm("mov.b64 %0, {%1, %2};" : "=l"(r) : "f"(a), "f"(b));
    return r;
}
__device__ __forceinline__ void fma2(unsigned long long& d,
                                     unsigned long long a,
                                     unsigned long long b) {
    asm("fma.rn.f32x2 %0, %1, %2, %0;" : "+l"(d) : "l"(a), "l"(b));
}
__device__ __forceinline__ float2 unpack2f(unsigned long long v) {
    float lo, hi;
    asm("mov.b64 {%0, %1}, %2;" : "=f"(lo), "=f"(hi) : "l"(v));
    float2 r; r.x = lo; r.y = hi;
    return r;
}
__device__ __forceinline__ float ex2f(float x) {
    float y; asm("ex2.approx.f32 %0, %1;" : "=f"(y) : "f"(x)); return y;
}
__device__ __forceinline__ float rcpf(float x) {
    float y; asm("rcp.approx.f32 %0, %1;" : "=f"(y) : "f"(x)); return y;
}

#define C2LOG2E 2.8853900817779268f   // 2*log2(e)

// ---------------- k1 smem layout (bytes) ----------------
// xq   : [64][260] floats  (xq[d][j], float4-grouped by jq; row 1040B)
// Bdup : [64][66] u64      (B row d, e-dup pairs; row 528B, 64 used)
// bw2  : 64 float2         (bat*2log2e, -aw)
// xi   : 64 f32
// A_s  : 256 f32
// p4   : 256*5 f32         (partial logits, stride 5; also agg partials)
// red  : 8 f32
// baseq: 4 f32
#define SM_XQ    0
#define SM_BD    66560
#define SM_BW2   100352
#define SM_XI    100864
#define SM_AS    101120
#define SM_P4    102144
#define SM_RED   107264
#define SM_BASEQ 107296
#define SM_TOT1  107312

// =====================================================================
// Kernel 1: attention logits + softmax + aggregation (FFMA2 tiled)
// grid (16 ichunks, 16 b), block 256, 2 CTAs/SM.
// Thread (eq = tid>>6, jq = tid&63): j in {4jq..4jq+3}, e in [16eq,16eq+16)
// =====================================================================
__global__ __launch_bounds__(256, 2)
void k1_attention(const float* __restrict__ x,
                  const float* __restrict__ Watt,
                  const float* __restrict__ batt_g,
                  const float* __restrict__ attw_g)
{
    extern __shared__ char sm[];
    float* A_s   = (float*)(sm + SM_AS);
    float* p4    = (float*)(sm + SM_P4);
    float* red   = (float*)(sm + SM_RED);
    float* xi    = (float*)(sm + SM_XI);
    float2* bw2  = (float2*)(sm + SM_BW2);
    float* baseq = (float*)(sm + SM_BASEQ);

    const int tid  = threadIdx.x;
    const int lane = tid & 31, wid = tid >> 5;
    const int eq   = tid >> 6;        // e-quarter 0..3
    const int jq   = tid & 63;        // j-group
    const int b    = blockIdx.y;
    const int i0   = blockIdx.x * 16;

    const float* xb = x + (size_t)b * NN * DD;

    // ---- one-time: xq[d][j] = x[b][j][d] (transposed, row stride 260 f) ----
    for (int idx = tid; idx < NN * DD; idx += 256) {
        int d = idx & 63, j = idx >> 6;
        ((float*)(sm + SM_XQ))[d * 260 + j] = xb[(size_t)j * DD + d];
    }
    if (tid < 64) {
        float aww = attw_g[tid];
        bw2[tid] = make_float2(batt_g[tid] * C2LOG2E, -aww);
    }
    __syncthreads();
    if (tid < 4) {
        float s = 0.f;
        #pragma unroll
        for (int e = 0; e < 16; ++e) s += -bw2[tid * 16 + e].y;  // aw
        baseq[tid] = 0.5f * s;
    }
    __syncthreads();

    // cached per-thread epilogue constants
    float2 bwr[16];
    #pragma unroll
    for (int e = 0; e < 16; ++e) bwr[e] = bw2[eq * 16 + e];
    const float bq = baseq[eq];

    // W row slice for B-build: thread builds (d = tid>>2, e0 = (tid&3)*16)
    const int bd_d = tid >> 2, bd_e0 = (tid & 3) * 16;
    const float4* wrow = (const float4*)(Watt + bd_d * 64 + bd_e0);

    for (int ii = 0; ii < 16; ++ii) {
        const int ig = i0 + ii;

        // (A) load x_i
        if (tid < 64) xi[tid] = xb[(size_t)ig * DD + tid];
        __syncthreads();

        // (B) build Bdup[d][e] = dup( W[d][e] * xi[d] )
        {
            float xd = xi[bd_d];
            unsigned long long* brow =
                (unsigned long long*)(sm + SM_BD) + bd_d * 66 + bd_e0;
            #pragma unroll
            for (int t = 0; t < 4; ++t) {
                float4 w = __ldg(wrow + t);
                brow[t * 4 + 0] = pack2f(w.x * xd, w.x * xd);
                brow[t * 4 + 1] = pack2f(w.y * xd, w.y * xd);
                brow[t * 4 + 2] = pack2f(w.z * xd, w.z * xd);
                brow[t * 4 + 3] = pack2f(w.w * xd, w.w * xd);
            }
        }
        __syncthreads();

        // (C) inner GEMM: acc[2e'+jp] (pairs over j) over 64 d
        unsigned long long acc[32];
        #pragma unroll
        for (int e = 0; e < 32; ++e) acc[e] = 0ull;

        {
            const char* xq_p = sm + SM_XQ + jq * 16;
            const char* bd_p = sm + SM_BD + eq * 128;
            #pragma unroll 8
            for (int d = 0; d < 64; ++d) {
                ulonglong2 xv = *(const ulonglong2*)(xq_p + d * 1040);
                const ulonglong2* br = (const ulonglong2*)(bd_p + d * 528);
                #pragma unroll
                for (int h = 0; h < 8; ++h) {
                    ulonglong2 bb = br[h];
                    fma2(acc[4 * h + 0], xv.x, bb.x);
                    fma2(acc[4 * h + 1], xv.y, bb.x);
                    fma2(acc[4 * h + 2], xv.x, bb.y);
                    fma2(acc[4 * h + 3], xv.y, bb.y);
                }
            }
        }

        // (D) epilogue: tanh via ex2/rcp, partial logits for 4 j's
        float pl0 = bq, pl1 = bq, pl2 = bq, pl3 = bq;
        #pragma unroll
        for (int e = 0; e < 16; ++e) {
            float2 bc = bwr[e];
            float2 v01 = unpack2f(acc[2 * e + 0]);
            float2 v23 = unpack2f(acc[2 * e + 1]);
            float r0 = rcpf(ex2f(fmaf(v01.x, C2LOG2E, bc.x)) + 1.f);
            float r1 = rcpf(ex2f(fmaf(v01.y, C2LOG2E, bc.x)) + 1.f);
            float r2 = rcpf(ex2f(fmaf(v23.x, C2LOG2E, bc.x)) + 1.f);
            float r3 = rcpf(ex2f(fmaf(v23.y, C2LOG2E, bc.x)) + 1.f);
            pl0 = fmaf(bc.y, r0, pl0);
            pl1 = fmaf(bc.y, r1, pl1);
            pl2 = fmaf(bc.y, r2, pl2);
            pl3 = fmaf(bc.y, r3, pl3);
        }
        // exchange partials: p4[j*5 + eq]
        p4[(4 * jq + 0) * 5 + eq] = pl0;
        p4[(4 * jq + 1) * 5 + eq] = pl1;
        p4[(4 * jq + 2) * 5 + eq] = pl2;
        p4[(4 * jq + 3) * 5 + eq] = pl3;
        __syncthreads();

        // (E) thread tid owns j = tid: combine + softmax over 256 j
        float logit = p4[tid * 5 + 0] + p4[tid * 5 + 1] +
                      p4[tid * 5 + 2] + p4[tid * 5 + 3];

        float m = logit;
        #pragma unroll
        for (int o = 16; o; o >>= 1) m = fmaxf(m, __shfl_xor_sync(0xffffffffu, m, o));
        if (lane == 0) red[wid] = m;
        __syncthreads();
        m = red[0];
        #pragma unroll
        for (int w = 1; w < 8; ++w) m = fmaxf(m, red[w]);
        float ex = ex2f((logit - m) * 1.4426950408889634f);
        float s = ex;
        #pragma unroll
        for (int o = 16; o; o >>= 1) s += __shfl_xor_sync(0xffffffffu, s, o);
        __syncthreads();
        if (lane == 0) red[wid] = s;
        __syncthreads();
        s = 0.f;
        #pragma unroll
        for (int w = 0; w < 8; ++w) s += red[w];
        A_s[tid] = ex / s;
        __syncthreads();

        // (F) agg[d] = sum_j A[j] * x[b][j][d]  (x from gmem, coalesced)
        {
            int q = tid >> 6, d = tid & 63;
            const float* xp = xb + (size_t)(q * 64) * DD + d;
            const float* Aq = A_s + q * 64;
            float pa = 0.f;
            #pragma unroll 8
            for (int jj = 0; jj < 64; ++jj) pa = fmaf(Aq[jj], xp[(size_t)jj * 64], pa);
            p4[tid] = pa;       // reuse p4 region (pl already consumed)
        }
        __syncthreads();
        if (tid < 64) {
            float a = p4[tid] + p4[tid + 64] + p4[tid + 128] + p4[tid + 192];
            g_agg[((size_t)b * NN + ig) * DD + tid] = a;
        }
        __syncthreads();
    }
}

// =====================================================================
// Kernel 2: h = agg@W_pwa + b + x@W_pna + b ; BN ; SELU ; scores
// =====================================================================
__global__ __launch_bounds__(256)
void k2_linear(const float* __restrict__ x,
               const float* __restrict__ Wpwa, const float* __restrict__ bpwa,
               const float* __restrict__ Wpna, const float* __restrict__ bpna,
               const float* __restrict__ bnsc, const float* __restrict__ bnbi,
               const float* __restrict__ poolw, const float* __restrict__ poolb)
{
    __shared__ float redsm[8];
    const int tid = threadIdx.x;
    const int g = tid >> 6, e = tid & 63;
    const int ilin = blockIdx.x * 4 + g;
    const float* agg = g_agg + (size_t)ilin * DD;
    const float* xi  = x + (size_t)ilin * DD;

    float h = bpwa[e] + bpna[e];
    #pragma unroll 8
    for (int d = 0; d < 64; ++d) {
        h = fmaf(__ldg(agg + d), __ldg(Wpwa + d * 64 + e), h);
        h = fmaf(__ldg(xi + d),  __ldg(Wpna + d * 64 + e), h);
    }
    h = h * (bnsc[e] * rsqrtf(1.0f + 1e-5f)) + bnbi[e];
    h = 1.0507009873554805f *
        (h > 0.f ? h : 1.6732632423543772f * (__expf(h) - 1.f));
    g_h[(size_t)ilin * DD + e] = h;

    float r = h * poolw[e];
    #pragma unroll
    for (int o = 16; o; o >>= 1) r += __shfl_xor_sync(0xffffffffu, r, o);
    const int lane = tid & 31, warp = tid >> 5;
    if (lane == 0) redsm[warp] = r;
    __syncthreads();
    if (e == 0) {
        float z = redsm[g * 2] + redsm[g * 2 + 1] + poolb[0];
        g_scores[ilin] = 1.f / (1.f + __expf(-z));
    }
}

// =====================================================================
// Kernel 3: stable top-k (jax.lax.top_k order) + gather of h*score
// =====================================================================
__global__ __launch_bounds__(256)
void k3_topk(float* __restrict__ out)
{
    __shared__ float sc[NN];
    __shared__ int src[KTOP];
    const int tid = threadIdx.x;
    const int b = blockIdx.x;

    float s = g_scores[b * NN + tid];
    sc[tid] = s;
    __syncthreads();

    int rank = 0;
    #pragma unroll 8
    for (int j = 0; j < NN; ++j) {
        float sj = sc[j];
        rank += (sj > s) || (sj == s && j < tid);
    }
    if (rank < KTOP) src[rank] = tid;
    __syncthreads();

    for (int idx = tid; idx < KTOP * DD; idx += 256) {
        int r = idx >> 6, e = idx & 63;
        int j = src[r];
        out[b * (KTOP * DD) + idx] = g_h[((size_t)b * NN + j) * DD + e] * sc[j];
    }
}

// =====================================================================
extern "C" void kernel_launch(void* const* d_in, const int* in_sizes, int n_in,
                              void* d_out, int out_size)
{
    const float* x     = (const float*)d_in[0];
    const float* Watt  = (const float*)d_in[1];
    const float* batt  = (const float*)d_in[2];
    const float* attw  = (const float*)d_in[3];
    const float* Wpwa  = (const float*)d_in[4];
    const float* bpwa  = (const float*)d_in[5];
    const float* Wpna  = (const float*)d_in[6];
    const float* bpna  = (const float*)d_in[7];
    const float* bnsc  = (const float*)d_in[8];
    const float* bnbi  = (const float*)d_in[9];
    const float* poolw = (const float*)d_in[10];
    const float* poolb = (const float*)d_in[11];

    cudaFuncSetAttribute(k1_attention,
                         cudaFuncAttributeMaxDynamicSharedMemorySize, SM_TOT1);

    dim3 g1(16, 16);   // x: i-chunk, y: batch
    k1_attention<<<g1, 256, SM_TOT1>>>(x, Watt, batt, attw);
    k2_linear<<<(BB * NN) / 4, 256>>>(x, Wpwa, bpwa, Wpna, bpna,
                                      bnsc, bnbi, poolw, poolb);
    k3_topk<<<BB, 256>>>((float*)d_out);
}

// round 5
// speedup vs baseline: 1.5936x; 1.4595x over previous
#include <cuda_runtime.h>
#include <math.h>
#include <stdint.h>

#define BB   16
#define NN   256
#define DD   64
#define KTOP 128
#define NT   8          // 256/32 tiles per dim
#define NPAIR 36        // NT*(NT+1)/2

// Scratch (no device allocations allowed)
__device__ float g_logits[BB * NN * NN];   // 4 MB
__device__ float g_agg[BB * NN * DD];
__device__ float g_h[BB * NN * DD];
__device__ float g_scores[BB * NN];

// ---------------- packed f32x2 helpers ----------------
__device__ __forceinline__ unsigned long long pack2f(float a, float b) {
    unsigned long long r;
    asm("mov.b64 %0, {%1, %2};" : "=l"(r) : "f"(a), "f"(b));
    return r;
}
__device__ __forceinline__ void fma2(unsigned long long& d,
                                     unsigned long long a,
                                     unsigned long long b) {
    asm("fma.rn.f32x2 %0, %1, %2, %0;" : "+l"(d) : "l"(a), "l"(b));
}
__device__ __forceinline__ unsigned long long mul2(unsigned long long a,
                                                   unsigned long long b) {
    unsigned long long r;
    asm("mul.rn.f32x2 %0, %1, %2;" : "=l"(r) : "l"(a), "l"(b));
    return r;
}
__device__ __forceinline__ float2 unpack2f(unsigned long long v) {
    float lo, hi;
    asm("mov.b64 {%0, %1}, %2;" : "=f"(lo), "=f"(hi) : "l"(v));
    float2 r; r.x = lo; r.y = hi;
    return r;
}
__device__ __forceinline__ float ex2f(float x) {
    float y; asm("ex2.approx.f32 %0, %1;" : "=f"(y) : "f"(x)); return y;
}
__device__ __forceinline__ float rcpf(float x) {
    float y; asm("rcp.approx.f32 %0, %1;" : "=f"(y) : "f"(x)); return y;
}

#define C2LOG2E 2.8853900817779268f   // 2*log2(e)

// ---------------- k1a smem layout (bytes) ----------------
// xip : [64][16] u64   i-pair values        8192
// xjd : [64][32] u64   j dup pairs         16384
// wdup: [64][68] u64   W dup pairs (eh-half at +34 u64, bank offset +4) 34816
// ep  : [8][32][2] f32 partial logits       2048
// bw2 : 64 float2      (bias*2log2e, -aw)    512
// base: 2 f32 (+pad)
#define SM_XIP  0
#define SM_XJD  8192
#define SM_WD   24576
#define SM_EP   59392
#define SM_BW   61440
#define SM_BASE 61952
#define SM_TOT1 61968

// =====================================================================
// Kernel 1a: symmetric logits. grid (36 tile-pairs, 16 b), block 256.
// CTA = (b, ti, tj) with ti<=tj; computes dense 32x32 logit tile and
// writes both [i,j] and [j,i]. 4 passes of 8 i-rows.
// Thread: ip = tid>>6 (i-pair), j = (tid>>1)&31, eh = tid&1 (e-half).
// acc[k] (u64, lanes = the 2 i's) holds e = eh*32 + k.
// =====================================================================
__global__ __launch_bounds__(256, 2)
void k1a_logits(const float* __restrict__ x,
                const float* __restrict__ Watt,
                const float* __restrict__ batt_g,
                const float* __restrict__ attw_g)
{
    extern __shared__ char sm[];
    unsigned long long* xip  = (unsigned long long*)(sm + SM_XIP);
    unsigned long long* xjd  = (unsigned long long*)(sm + SM_XJD);
    unsigned long long* wdup = (unsigned long long*)(sm + SM_WD);
    float*  ep   = (float*)(sm + SM_EP);
    float2* bw2  = (float2*)(sm + SM_BW);
    float*  base = (float*)(sm + SM_BASE);

    const int tid = threadIdx.x;
    const int b   = blockIdx.y;

    // decode triangle tile pair
    int p = blockIdx.x, ti = 0;
    while (p >= NT - ti) { p -= NT - ti; ++ti; }
    const int tj = ti + p;
    const int i0 = ti * 32, j0 = tj * 32;

    const float* xb = x + (size_t)b * NN * DD;

    // ---- build smem operands ----
    for (int t = tid; t < 1024; t += 256) {          // xip[d][ipg]
        int ipg = t >> 6, d = t & 63;
        float a = xb[(size_t)(i0 + 2 * ipg) * DD + d];
        float c = xb[(size_t)(i0 + 2 * ipg + 1) * DD + d];
        xip[d * 16 + ipg] = pack2f(a, c);
    }
    for (int t = tid; t < 2048; t += 256) {          // xjd[d][j] dup
        int j = t >> 6, d = t & 63;
        float v = xb[(size_t)(j0 + j) * DD + d];
        xjd[d * 32 + j] = pack2f(v, v);
    }
    for (int t = tid; t < 4096; t += 256) {          // wdup[d][slot] dup
        int d = t >> 6, e = t & 63;
        float w = __ldg(Watt + t);
        int slot = (e < 32) ? e : (e + 2);           // eh=1 at +34
        wdup[d * 68 + slot] = pack2f(w, w);
    }
    if (tid < 64) {
        float aww = attw_g[tid];
        bw2[tid] = make_float2(batt_g[tid] * C2LOG2E, -aww);
    }
    __syncthreads();
    if (tid < 2) {
        float s = 0.f;
        #pragma unroll
        for (int e = 0; e < 32; ++e) s -= bw2[tid * 32 + e].y;   // +aw
        base[tid] = 0.5f * s;
    }
    __syncthreads();

    const int ip = tid >> 6;            // 0..3
    const int jl = (tid >> 1) & 31;     // j lane
    const int eh = tid & 1;             // e half

    const unsigned long long* xip_p = xip + ip;     // + pass*4, + d*16
    const unsigned long long* xjd_p = xjd + jl;     // + d*32
    const char* wd_p = (const char*)(wdup + eh * 34);

    for (int pass = 0; pass < 4; ++pass) {
        unsigned long long acc[32];
        #pragma unroll
        for (int k = 0; k < 32; ++k) acc[k] = 0ull;

        const unsigned long long* xv = xip_p + pass * 4;

        #pragma unroll 4
        for (int d = 0; d < 64; ++d) {
            unsigned long long xp = xv[d * 16];
            unsigned long long xj = xjd_p[d * 32];
            unsigned long long pp = mul2(xp, xj);
            const ulonglong2* wr = (const ulonglong2*)(wd_p + d * 544);
            #pragma unroll
            for (int h = 0; h < 16; ++h) {
                ulonglong2 wv = wr[h];
                fma2(acc[2 * h + 0], pp, wv.x);
                fma2(acc[2 * h + 1], pp, wv.y);
            }
        }

        // epilogue: tanh + dot(aw) for the two i-lanes
        float pl0 = base[eh], pl1 = base[eh];
        #pragma unroll
        for (int k = 0; k < 32; ++k) {
            float2 bc = bw2[eh * 32 + k];
            float2 v = unpack2f(acc[k]);
            float r0 = rcpf(ex2f(fmaf(v.x, C2LOG2E, bc.x)) + 1.f);
            float r1 = rcpf(ex2f(fmaf(v.y, C2LOG2E, bc.x)) + 1.f);
            pl0 = fmaf(bc.y, r0, pl0);
            pl1 = fmaf(bc.y, r1, pl1);
        }
        ep[(2 * ip + 0) * 64 + jl * 2 + eh] = pl0;
        ep[(2 * ip + 1) * 64 + jl * 2 + eh] = pl1;
        __syncthreads();

        // combine eh halves: thread t -> (il = t>>5, jj = t&31)
        {
            float lg = ep[tid * 2] + ep[tid * 2 + 1];
            int il = tid >> 5, jj = tid & 31;
            int irow = i0 + pass * 8 + il;
            int jcol = j0 + jj;
            g_logits[((size_t)b * NN + irow) * NN + jcol] = lg;
            g_logits[((size_t)b * NN + jcol) * NN + irow] = lg;
        }
        __syncthreads();
    }
}

// =====================================================================
// Kernel 1b: softmax over j + aggregation. grid (16 ichunks, 16 b).
// =====================================================================
__global__ __launch_bounds__(256, 2)
void k1b_softmax_agg(const float* __restrict__ x)
{
    __shared__ float A_s[NN];
    __shared__ float part[NN];
    __shared__ float red[8];

    const int tid = threadIdx.x;
    const int lane = tid & 31, wid = tid >> 5;
    const int b  = blockIdx.y;
    const int i0 = blockIdx.x * 16;
    const float* xb = x + (size_t)b * NN * DD;

    for (int ii = 0; ii < 16; ++ii) {
        const int ig = i0 + ii;
        float logit = g_logits[((size_t)b * NN + ig) * NN + tid];

        float m = logit;
        #pragma unroll
        for (int o = 16; o; o >>= 1) m = fmaxf(m, __shfl_xor_sync(0xffffffffu, m, o));
        if (lane == 0) red[wid] = m;
        __syncthreads();
        m = red[0];
        #pragma unroll
        for (int w = 1; w < 8; ++w) m = fmaxf(m, red[w]);
        float ex = ex2f((logit - m) * 1.4426950408889634f);
        float s = ex;
        #pragma unroll
        for (int o = 16; o; o >>= 1) s += __shfl_xor_sync(0xffffffffu, s, o);
        __syncthreads();
        if (lane == 0) red[wid] = s;
        __syncthreads();
        s = 0.f;
        #pragma unroll
        for (int w = 0; w < 8; ++w) s += red[w];
        A_s[tid] = ex / s;
        __syncthreads();

        // agg[d] = sum_j A[j] * x[b][j][d]
        {
            int q = tid >> 6, d = tid & 63;
            const float* xp = xb + (size_t)(q * 64) * DD + d;
            const float* Aq = A_s + q * 64;
            float pa = 0.f;
            #pragma unroll 8
            for (int jj = 0; jj < 64; ++jj) pa = fmaf(Aq[jj], xp[(size_t)jj * 64], pa);
            part[tid] = pa;
        }
        __syncthreads();
        if (tid < 64) {
            float a = part[tid] + part[tid + 64] + part[tid + 128] + part[tid + 192];
            g_agg[((size_t)b * NN + ig) * DD + tid] = a;
        }
        __syncthreads();
    }
}

// =====================================================================
// Kernel 2: h = agg@W_pwa + b + x@W_pna + b ; BN ; SELU ; scores
// =====================================================================
__global__ __launch_bounds__(256)
void k2_linear(const float* __restrict__ x,
               const float* __restrict__ Wpwa, const float* __restrict__ bpwa,
               const float* __restrict__ Wpna, const float* __restrict__ bpna,
               const float* __restrict__ bnsc, const float* __restrict__ bnbi,
               const float* __restrict__ poolw, const float* __restrict__ poolb)
{
    __shared__ float redsm[8];
    const int tid = threadIdx.x;
    const int g = tid >> 6, e = tid & 63;
    const int ilin = blockIdx.x * 4 + g;
    const float* agg = g_agg + (size_t)ilin * DD;
    const float* xi  = x + (size_t)ilin * DD;

    float h = bpwa[e] + bpna[e];
    #pragma unroll 8
    for (int d = 0; d < 64; ++d) {
        h = fmaf(__ldg(agg + d), __ldg(Wpwa + d * 64 + e), h);
        h = fmaf(__ldg(xi + d),  __ldg(Wpna + d * 64 + e), h);
    }
    h = h * (bnsc[e] * rsqrtf(1.0f + 1e-5f)) + bnbi[e];
    h = 1.0507009873554805f *
        (h > 0.f ? h : 1.6732632423543772f * (__expf(h) - 1.f));
    g_h[(size_t)ilin * DD + e] = h;

    float r = h * poolw[e];
    #pragma unroll
    for (int o = 16; o; o >>= 1) r += __shfl_xor_sync(0xffffffffu, r, o);
    const int lane = tid & 31, warp = tid >> 5;
    if (lane == 0) redsm[warp] = r;
    __syncthreads();
    if (e == 0) {
        float z = redsm[g * 2] + redsm[g * 2 + 1] + poolb[0];
        g_scores[ilin] = 1.f / (1.f + __expf(-z));
    }
}

// =====================================================================
// Kernel 3: stable top-k (jax.lax.top_k order) + gather of h*score
// =====================================================================
__global__ __launch_bounds__(256)
void k3_topk(float* __restrict__ out)
{
    __shared__ float sc[NN];
    __shared__ int src[KTOP];
    const int tid = threadIdx.x;
    const int b = blockIdx.x;

    float s = g_scores[b * NN + tid];
    sc[tid] = s;
    __syncthreads();

    int rank = 0;
    #pragma unroll 8
    for (int j = 0; j < NN; ++j) {
        float sj = sc[j];
        rank += (sj > s) || (sj == s && j < tid);
    }
    if (rank < KTOP) src[rank] = tid;
    __syncthreads();

    for (int idx = tid; idx < KTOP * DD; idx += 256) {
        int r = idx >> 6, e = idx & 63;
        int j = src[r];
        out[b * (KTOP * DD) + idx] = g_h[((size_t)b * NN + j) * DD + e] * sc[j];
    }
}

// =====================================================================
extern "C" void kernel_launch(void* const* d_in, const int* in_sizes, int n_in,
                              void* d_out, int out_size)
{
    const float* x     = (const float*)d_in[0];
    const float* Watt  = (const float*)d_in[1];
    const float* batt  = (const float*)d_in[2];
    const float* attw  = (const float*)d_in[3];
    const float* Wpwa  = (const float*)d_in[4];
    const float* bpwa  = (const float*)d_in[5];
    const float* Wpna  = (const float*)d_in[6];
    const float* bpna  = (const float*)d_in[7];
    const float* bnsc  = (const float*)d_in[8];
    const float* bnbi  = (const float*)d_in[9];
    const float* poolw = (const float*)d_in[10];
    const float* poolb = (const float*)d_in[11];

    cudaFuncSetAttribute(k1a_logits,
                         cudaFuncAttributeMaxDynamicSharedMemorySize, SM_TOT1);

    dim3 ga(NPAIR, BB);
    k1a_logits<<<ga, 256, SM_TOT1>>>(x, Watt, batt, attw);
    dim3 gb(16, BB);
    k1b_softmax_agg<<<gb, 256>>>(x);
    k2_linear<<<(BB * NN) / 4, 256>>>(x, Wpwa, bpwa, Wpna, bpna,
                                      bnsc, bnbi, poolw, poolb);
    k3_topk<<<BB, 256>>>((float*)d_out);
}